// round 16
// baseline (speedup 1.0000x reference)
#include <cuda_runtime.h>
#include <cuda_fp16.h>
#include <math.h>
#include <stdint.h>

// Problem constants
#define B_N   16
#define N_TOK 1024
#define DIM_N 768
#define H_N   12
#define QKVD  2304
#define MROWS 16384
#define SCALE_C 0.125f
#define LOG2E 1.4426950408889634f
#define MSHIFT 4.0f
#define LN_EPS  1e-5f

// Scratch (device globals — no dynamic allocation allowed). All fp16.
__device__ __half g_xn[(size_t)MROWS * DIM_N];
__device__ __half g_qkv[(size_t)MROWS * QKVD];
__device__ __half g_att[(size_t)MROWS * DIM_N];
__device__ __half g_wq[(size_t)QKVD * DIM_N];
__device__ __half g_wp[(size_t)DIM_N * DIM_N];

// ---------------------------------------------------------------------------
// PTX helpers
// ---------------------------------------------------------------------------
__device__ __forceinline__ uint32_t sptr(const void* p) {
    return (uint32_t)__cvta_generic_to_shared(p);
}
__device__ __forceinline__ void ldmx4(uint32_t* r, uint32_t a) {
    asm volatile("ldmatrix.sync.aligned.m8n8.x4.shared.b16 {%0,%1,%2,%3}, [%4];"
                 : "=r"(r[0]), "=r"(r[1]), "=r"(r[2]), "=r"(r[3]) : "r"(a));
}
__device__ __forceinline__ void ldmx4t(uint32_t* r, uint32_t a) {
    asm volatile("ldmatrix.sync.aligned.m8n8.x4.trans.shared.b16 {%0,%1,%2,%3}, [%4];"
                 : "=r"(r[0]), "=r"(r[1]), "=r"(r[2]), "=r"(r[3]) : "r"(a));
}
__device__ __forceinline__ void mma16816(float* c, const uint32_t* a,
                                         uint32_t b0, uint32_t b1) {
    asm volatile(
        "mma.sync.aligned.m16n8k16.row.col.f32.f16.f16.f32 "
        "{%0,%1,%2,%3}, {%4,%5,%6,%7}, {%8,%9}, {%0,%1,%2,%3};"
        : "+f"(c[0]), "+f"(c[1]), "+f"(c[2]), "+f"(c[3])
        : "r"(a[0]), "r"(a[1]), "r"(a[2]), "r"(a[3]), "r"(b0), "r"(b1));
}
__device__ __forceinline__ uint32_t packh2(float x, float y) {
    __half2 h = __floats2half2_rn(x, y);
    return *(uint32_t*)&h;
}
__device__ __forceinline__ uint32_t ex2h2(uint32_t x) {
    uint32_t r;
    asm("ex2.approx.f16x2 %0, %1;" : "=r"(r) : "r"(x));
    return r;
}
// Packed fp32x2 FMA (Blackwell): d = a * sc + c, per lane, .rn — then to half2.
__device__ __forceinline__ uint32_t fma2h2(float x0, float x1,
                                           float b0, float b1, uint64_t sc) {
    uint64_t a, c, d;
    asm("mov.b64 %0, {%1, %2};" : "=l"(a) : "f"(x0), "f"(x1));
    asm("mov.b64 %0, {%1, %2};" : "=l"(c) : "f"(b0), "f"(b1));
    asm("fma.rn.f32x2 %0, %1, %2, %3;" : "=l"(d) : "l"(a), "l"(sc), "l"(c));
    float r0, r1;
    asm("mov.b64 {%0, %1}, %2;" : "=f"(r0), "=f"(r1) : "l"(d));
    return packh2(r0, r1);
}
#define CP_ASYNC(dst, src) \
    asm volatile("cp.async.cg.shared.global [%0], [%1], 16;" :: "r"(dst), "l"(src))
#define CP_COMMIT() asm volatile("cp.async.commit_group;")
#define CP_WAITN(n) asm volatile("cp.async.wait_group %0;" :: "n"(n))

// ---------------------------------------------------------------------------
// Kernel 0+1 merged: LayerNorm (blocks [0, MROWS/8)) + weight cvt (rest).
// ---------------------------------------------------------------------------
#define LN_BLOCKS (MROWS / 8)
#define NCVT ((QKVD + DIM_N) * DIM_N)
#define CVT_BLOCKS (NCVT / 1024)

__global__ void prep_kernel(const float* __restrict__ x,
                            const float* __restrict__ w,
                            const float* __restrict__ b,
                            const float* __restrict__ wq_f,
                            const float* __restrict__ wp_f,
                            __half* __restrict__ wq_h,
                            __half* __restrict__ wp_h) {
    if (blockIdx.x < LN_BLOCKS) {
        int warp = threadIdx.x >> 5, lane = threadIdx.x & 31;
        int row = blockIdx.x * 8 + warp;
        const float4* xr = (const float4*)(x + (size_t)row * DIM_N);
        float4 v[6];
        float s = 0.0f, sq = 0.0f;
        #pragma unroll
        for (int j = 0; j < 6; j++) {
            v[j] = xr[lane + 32 * j];
            s  += v[j].x + v[j].y + v[j].z + v[j].w;
            sq += v[j].x * v[j].x + v[j].y * v[j].y
                + v[j].z * v[j].z + v[j].w * v[j].w;
        }
        #pragma unroll
        for (int o = 16; o; o >>= 1) {
            s  += __shfl_xor_sync(0xffffffffu, s, o);
            sq += __shfl_xor_sync(0xffffffffu, sq, o);
        }
        float mean = s * (1.0f / DIM_N);
        float var  = sq * (1.0f / DIM_N) - mean * mean;
        float rstd = rsqrtf(var + LN_EPS);
        uint2* orow = (uint2*)(g_xn + (size_t)row * DIM_N);
        const float4* wv = (const float4*)w;
        const float4* bv = (const float4*)b;
        #pragma unroll
        for (int j = 0; j < 6; j++) {
            int idx = lane + 32 * j;
            float4 wj = wv[idx], bj = bv[idx];
            float o0 = (v[j].x - mean) * rstd * wj.x + bj.x;
            float o1 = (v[j].y - mean) * rstd * wj.y + bj.y;
            float o2 = (v[j].z - mean) * rstd * wj.z + bj.z;
            float o3 = (v[j].w - mean) * rstd * wj.w + bj.w;
            orow[idx] = make_uint2(packh2(o0, o1), packh2(o2, o3));
        }
    } else {
        const int NQ = QKVD * DIM_N;
        int i = ((blockIdx.x - LN_BLOCKS) * 256 + threadIdx.x) * 4;
        if (i < NQ) {
            float4 v = *(const float4*)(wq_f + i);
            *(__half2*)(wq_h + i)     = __floats2half2_rn(v.x, v.y);
            *(__half2*)(wq_h + i + 2) = __floats2half2_rn(v.z, v.w);
        } else {
            int k = i - NQ;
            if (k < DIM_N * DIM_N) {
                float4 v = *(const float4*)(wp_f + k);
                *(__half2*)(wp_h + k)     = __floats2half2_rn(v.x, v.y);
                *(__half2*)(wp_h + k + 2) = __floats2half2_rn(v.z, v.w);
            }
        }
    }
}

// ---------------------------------------------------------------------------
// Kernel 2/4: fp16 HMMA GEMM — A-fragment ping-pong (hide the 4-ldm chain),
// B loaded fresh per ks (2-ldm, covered by the A-prefetch issue slack).
// 128x128 tile, BK=64, 8 warps (2x4), warp 64x32, 2 CTAs/SM, 3-stage ring.
// ---------------------------------------------------------------------------
#define G_STGB 32768
#define G_SMEM (3 * G_STGB)

template <int OUT_HALF>
__global__ void __launch_bounds__(256, 2)
hgemm_bias(const __half* __restrict__ A, const __half* __restrict__ W,
           const float* __restrict__ bias, void* __restrict__ Cv,
           int M, int J, int K) {
    extern __shared__ __align__(1024) char smg[];
    uint32_t sb = sptr(smg);

    int m0 = blockIdx.y * 128, j0 = blockIdx.x * 128;
    int tid = threadIdx.x, warp = tid >> 5, lane = tid & 31;
    int gid = lane >> 2, tig = lane & 3;
    int wm = (warp >> 2) * 64, wn = (warp & 3) * 32;
    int lr = tid >> 1, side = tid & 1;

    const __half* Ap = A + (size_t)(m0 + lr) * K + side * 32;
    const __half* Wp = W + (size_t)(j0 + lr) * K + side * 32;

    uint32_t sw[4];
    #pragma unroll
    for (int j = 0; j < 4; j++) {
        int c = side * 4 + j;
        sw[j] = (lr * 64 + ((c ^ (lr & 7)) * 8)) * 2;
    }

    auto fill = [&](int c, int s) {
        uint32_t as = sb + s * G_STGB;
        uint32_t bs = as + 16384;
        #pragma unroll
        for (int j = 0; j < 4; j++) {
            CP_ASYNC(as + sw[j], Ap + c * 64 + 8 * j);
            CP_ASYNC(bs + sw[j], Wp + c * 64 + 8 * j);
        }
        CP_COMMIT();
    };

    int tile = lane >> 3, rlow = lane & 7;
    int rowin = (tile & 1) * 8 + rlow;
    int chsel = tile >> 1;

    float acc[4][4][4];
    #pragma unroll
    for (int mt = 0; mt < 4; mt++)
        #pragma unroll
        for (int nt = 0; nt < 4; nt++)
            #pragma unroll
            for (int e = 0; e < 4; e++) acc[mt][nt][e] = 0.0f;

    int nk = K / 64;
    fill(0, 0); fill(1, 1); fill(2, 2);

    for (int i = 0; i < nk; i++) {
        if (i == 0)           { CP_WAITN(2); }
        else if (i < nk - 1)  { CP_WAITN(1); }
        else                  { CP_WAITN(0); }
        __syncthreads();
        if (i >= 1 && i + 2 < nk) fill(i + 2, (i + 2) % 3);

        int s = i - (i / 3) * 3;
        uint32_t Ab = sb + s * G_STGB, Bb = Ab + 16384;

        // A-fragment ping-pong: preload ks=0
        uint32_t afr[2][16];
        {
            int ch0 = (chsel ^ rlow) * 8;
            #pragma unroll
            for (int mt = 0; mt < 4; mt++)
                ldmx4(&afr[0][mt * 4], Ab + ((wm + mt * 16 + rowin) * 64 + ch0) * 2);
        }
        #pragma unroll
        for (int ks = 0; ks < 4; ks++) {
            int cur = ks & 1;
            int chunk = ((2 * ks + chsel) ^ rlow) * 8;
            // B fresh (2 ldm)
            uint32_t bf[8];
            ldmx4(&bf[0], Bb + ((wn + rowin) * 64 + chunk) * 2);
            ldmx4(&bf[4], Bb + ((wn + 16 + rowin) * 64 + chunk) * 2);
            // A prefetch for next ks (issues between B-load and MMAs)
            if (ks < 3) {
                int chn = ((2 * (ks + 1) + chsel) ^ rlow) * 8;
                #pragma unroll
                for (int mt = 0; mt < 4; mt++)
                    ldmx4(&afr[cur ^ 1][mt * 4],
                          Ab + ((wm + mt * 16 + rowin) * 64 + chn) * 2);
            }
            #pragma unroll
            for (int g = 0; g < 2; g++) {
                const uint32_t* r4 = &bf[g * 4];
                #pragma unroll
                for (int mt = 0; mt < 4; mt++) {
                    mma16816(acc[mt][2 * g],     &afr[cur][mt * 4], r4[0], r4[2]);
                    mma16816(acc[mt][2 * g + 1], &afr[cur][mt * 4], r4[1], r4[3]);
                }
            }
        }
    }

    #pragma unroll
    for (int mt = 0; mt < 4; mt++) {
        int row0 = m0 + wm + mt * 16 + gid;
        #pragma unroll
        for (int nt = 0; nt < 4; nt++) {
            int col = j0 + wn + nt * 8 + tig * 2;
            float b0 = bias[col], b1 = bias[col + 1];
            if (OUT_HALF) {
                __half* C = (__half*)Cv;
                *(uint32_t*)&C[(size_t)row0 * J + col] =
                    packh2(acc[mt][nt][0] + b0, acc[mt][nt][1] + b1);
                *(uint32_t*)&C[(size_t)(row0 + 8) * J + col] =
                    packh2(acc[mt][nt][2] + b0, acc[mt][nt][3] + b1);
            } else {
                float* C = (float*)Cv;
                *(float2*)&C[(size_t)row0 * J + col] =
                    make_float2(acc[mt][nt][0] + b0, acc[mt][nt][1] + b1);
                *(float2*)&C[(size_t)(row0 + 8) * J + col] =
                    make_float2(acc[mt][nt][2] + b0, acc[mt][nt][3] + b1);
            }
        }
    }
}

// ---------------------------------------------------------------------------
// Kernel 3: fused flash attention (R15 — control).
// ---------------------------------------------------------------------------
#define ATTN_SMEM 102528

__global__ void __launch_bounds__(256, 2)
attn_kernel(const float* __restrict__ biases) {
    extern __shared__ __align__(1024) char sma[];
    float* b_s = (float*)(sma + 98304);
    uint32_t Kb = sptr(sma);
    uint32_t Vb = Kb + 49152;
    __half* Qstage = (__half*)(sma + 49152);

    int qt = blockIdx.x, h = blockIdx.y, b = blockIdx.z;
    int tid = threadIdx.x, warp = tid >> 5, lane = tid & 31;
    int gid = lane >> 2, tig = lane & 3;
    int n0 = qt * 128;
    const float SCALE2 = SCALE_C * LOG2E;
    uint64_t sc2;
    asm("mov.b64 %0, {%1, %1};" : "=l"(sc2) : "f"(SCALE2));

    for (int i = tid; i < 1024; i += 256) {
        int dy = i >> 5, dx = i & 31;
        b_s[dx * 33 + dy] = biases[h * 1024 + i] * LOG2E - MSHIFT;
    }

    {
        int r = tid >> 1, side = tid & 1;
        const __half* qp = g_qkv + (size_t)(b * N_TOK + n0 + r) * QKVD
                           + h * 192 + side * 32;
        #pragma unroll
        for (int j = 0; j < 4; j++) {
            int c = side * 4 + j;
            *(uint4*)&Qstage[r * 64 + ((c ^ (r & 7)) * 8)] =
                *(const uint4*)(qp + 8 * j);
        }
    }
    __syncthreads();

    int tile = lane >> 3, rlow = lane & 7;
    int rowin = (tile & 1) * 8 + rlow;
    int chsel = tile >> 1;

    uint32_t qfrag[4][4];
    #pragma unroll
    for (int ks = 0; ks < 4; ks++) {
        int chunk = ((2 * ks + chsel) ^ rlow) * 8;
        ldmx4(qfrag[ks], Vb + ((warp * 16 + rowin) * 64 + chunk) * 2);
    }
    __syncthreads();

    uint32_t ones01 = (gid == 0) ? 0x3C003C00u : 0u;

    int q0 = n0 + warp * 16 + gid, q1 = q0 + 8;
    int yq0 = q0 >> 5, xq0 = q0 & 31;
    int yq1 = q1 >> 5, xq1 = q1 & 31;
    int dx0t[8], dx1t[8];
    #pragma unroll
    for (int v = 0; v < 8; v++) {
        int xm = (v >> 1) * 8 + tig * 2 + (v & 1);
        dx0t[v] = abs(xq0 - xm) * 33;
        dx1t[v] = abs(xq1 - xm) * 33;
    }

    int fr = tid >> 2, fq = tid & 3;
    uint32_t fsw[2];
    #pragma unroll
    for (int j = 0; j < 2; j++) {
        int c = fq * 2 + j;
        fsw[j] = (fr * 64 + ((c ^ (fr & 7)) * 8)) * 2;
    }
    auto fillkv2 = [&](int j2, int s) {
        #pragma unroll
        for (int t = 0; t < 2; t++) {
            int kt = 2 * j2 + t;
            const __half* kp = g_qkv + (size_t)(b * N_TOK + kt * 64 + fr) * QKVD
                               + h * 192 + 64 + fq * 16;
            const __half* vp = kp + 64;
            uint32_t off = s * 16384 + t * 8192;
            #pragma unroll
            for (int j = 0; j < 2; j++) {
                CP_ASYNC(Kb + off + fsw[j], kp + 8 * j);
                CP_ASYNC(Vb + off + fsw[j], vp + 8 * j);
            }
        }
        CP_COMMIT();
    };

    float oacc[8][4], lacc[4];
    #pragma unroll
    for (int nt = 0; nt < 8; nt++)
        #pragma unroll
        for (int e = 0; e < 4; e++) oacc[nt][e] = 0.0f;
    #pragma unroll
    for (int e = 0; e < 4; e++) lacc[e] = 0.0f;

    fillkv2(0, 0); fillkv2(1, 1); fillkv2(2, 2);

    for (int j2 = 0; j2 < 8; j2++) {
        if (j2 == 0)      { CP_WAITN(2); }
        else if (j2 < 7)  { CP_WAITN(1); }
        else              { CP_WAITN(0); }
        __syncthreads();
        if (j2 >= 1 && j2 + 2 < 8) fillkv2(j2 + 2, (j2 + 2) % 3);

        int s = j2 - (j2 / 3) * 3;
        #pragma unroll
        for (int t = 0; t < 2; t++) {
            int tt = 2 * j2 + t;
            uint32_t Kcur = Kb + s * 16384 + t * 8192;
            uint32_t Vcur = Vb + s * 16384 + t * 8192;

            float sacc[8][4];
            #pragma unroll
            for (int nt = 0; nt < 8; nt++)
                #pragma unroll
                for (int e = 0; e < 4; e++) sacc[nt][e] = 0.0f;

            #pragma unroll
            for (int ks = 0; ks < 4; ks++) {
                int chunk = ((2 * ks + chsel) ^ rlow) * 8;
                #pragma unroll
                for (int g = 0; g < 2; g++) {
                    uint32_t r4[4];
                    ldmx4(r4, Kcur + ((g * 16 + rowin) * 64 + chunk) * 2);
                    mma16816(sacc[2 * g],     qfrag[ks], r4[0], r4[2]);
                    mma16816(sacc[2 * g + 1], qfrag[ks], r4[1], r4[3]);
                }
            }
            #pragma unroll
            for (int ks = 0; ks < 4; ks++) {
                int chunk = ((2 * ks + chsel) ^ rlow) * 8;
                #pragma unroll
                for (int g = 2; g < 4; g++) {
                    uint32_t r4[4];
                    ldmx4(r4, Kcur + ((g * 16 + rowin) * 64 + chunk) * 2);
                    mma16816(sacc[2 * g],     qfrag[ks], r4[0], r4[2]);
                    mma16816(sacc[2 * g + 1], qfrag[ks], r4[1], r4[3]);
                }
            }

            uint32_t vfA0[4][4];
            #pragma unroll
            for (int g = 0; g < 4; g++) {
                int row = rowin;
                ldmx4t(vfA0[g], Vcur + (row * 64 + (((2 * g + chsel) ^ (row & 7)) * 8)) * 2);
            }

            int dy0A = abs(yq0 - 2 * tt), dy1A = abs(yq1 - 2 * tt);
            uint32_t pfragA[2][4];
            #pragma unroll
            for (int c = 0; c < 2; c++) {
                int v0 = (2 * c) * 2, v1 = (2 * c + 1) * 2;
                pfragA[c][0] = ex2h2(fma2h2(sacc[2 * c][0], sacc[2 * c][1],
                                            b_s[dx0t[v0] + dy0A],
                                            b_s[dx0t[v0 + 1] + dy0A], sc2));
                pfragA[c][1] = ex2h2(fma2h2(sacc[2 * c][2], sacc[2 * c][3],
                                            b_s[dx1t[v0] + dy1A],
                                            b_s[dx1t[v0 + 1] + dy1A], sc2));
                pfragA[c][2] = ex2h2(fma2h2(sacc[2 * c + 1][0], sacc[2 * c + 1][1],
                                            b_s[dx0t[v1] + dy0A],
                                            b_s[dx0t[v1 + 1] + dy0A], sc2));
                pfragA[c][3] = ex2h2(fma2h2(sacc[2 * c + 1][2], sacc[2 * c + 1][3],
                                            b_s[dx1t[v1] + dy1A],
                                            b_s[dx1t[v1 + 1] + dy1A], sc2));
            }

            mma16816(lacc, pfragA[0], ones01, ones01);
            #pragma unroll
            for (int g = 0; g < 4; g++) {
                mma16816(oacc[2 * g],     pfragA[0], vfA0[g][0], vfA0[g][1]);
                mma16816(oacc[2 * g + 1], pfragA[0], vfA0[g][2], vfA0[g][3]);
            }
            mma16816(lacc, pfragA[1], ones01, ones01);
            #pragma unroll
            for (int g = 0; g < 4; g++) {
                uint32_t r4[4];
                int row = 16 + rowin;
                ldmx4t(r4, Vcur + (row * 64 + (((2 * g + chsel) ^ (row & 7)) * 8)) * 2);
                mma16816(oacc[2 * g],     pfragA[1], r4[0], r4[1]);
                mma16816(oacc[2 * g + 1], pfragA[1], r4[2], r4[3]);
            }

            uint32_t vfB0[4][4];
            #pragma unroll
            for (int g = 0; g < 4; g++) {
                int row = 32 + rowin;
                ldmx4t(vfB0[g], Vcur + (row * 64 + (((2 * g + chsel) ^ (row & 7)) * 8)) * 2);
            }

            int dy0B = abs(yq0 - 2 * tt - 1), dy1B = abs(yq1 - 2 * tt - 1);
            uint32_t pfragB[2][4];
            #pragma unroll
            for (int c = 0; c < 2; c++) {
                int v0 = (2 * c) * 2, v1 = (2 * c + 1) * 2;
                pfragB[c][0] = ex2h2(fma2h2(sacc[4 + 2 * c][0], sacc[4 + 2 * c][1],
                                            b_s[dx0t[v0] + dy0B],
                                            b_s[dx0t[v0 + 1] + dy0B], sc2));
                pfragB[c][1] = ex2h2(fma2h2(sacc[4 + 2 * c][2], sacc[4 + 2 * c][3],
                                            b_s[dx1t[v0] + dy1B],
                                            b_s[dx1t[v0 + 1] + dy1B], sc2));
                pfragB[c][2] = ex2h2(fma2h2(sacc[5 + 2 * c][0], sacc[5 + 2 * c][1],
                                            b_s[dx0t[v1] + dy0B],
                                            b_s[dx0t[v1 + 1] + dy0B], sc2));
                pfragB[c][3] = ex2h2(fma2h2(sacc[5 + 2 * c][2], sacc[5 + 2 * c][3],
                                            b_s[dx1t[v1] + dy1B],
                                            b_s[dx1t[v1 + 1] + dy1B], sc2));
            }

            mma16816(lacc, pfragB[0], ones01, ones01);
            #pragma unroll
            for (int g = 0; g < 4; g++) {
                mma16816(oacc[2 * g],     pfragB[0], vfB0[g][0], vfB0[g][1]);
                mma16816(oacc[2 * g + 1], pfragB[0], vfB0[g][2], vfB0[g][3]);
            }
            mma16816(lacc, pfragB[1], ones01, ones01);
            #pragma unroll
            for (int g = 0; g < 4; g++) {
                uint32_t r4[4];
                int row = 48 + rowin;
                ldmx4t(r4, Vcur + (row * 64 + (((2 * g + chsel) ^ (row & 7)) * 8)) * 2);
                mma16816(oacc[2 * g],     pfragB[1], r4[0], r4[1]);
                mma16816(oacc[2 * g + 1], pfragB[1], r4[2], r4[3]);
            }
        }
    }

    float l0 = __shfl_sync(0xffffffffu, lacc[0], lane & 28);
    float l1 = __shfl_sync(0xffffffffu, lacc[2], lane & 28);
    float inv0 = 1.0f / l0, inv1 = 1.0f / l1;
    size_t row0 = (size_t)(b * N_TOK + n0 + warp * 16 + gid) * DIM_N;
    size_t row1 = row0 + 8 * DIM_N;
    #pragma unroll
    for (int nt = 0; nt < 8; nt++) {
        int col = h * 64 + nt * 8 + tig * 2;
        *(uint32_t*)&g_att[row0 + col] =
            packh2(oacc[nt][0] * inv0, oacc[nt][1] * inv0);
        *(uint32_t*)&g_att[row1 + col] =
            packh2(oacc[nt][2] * inv1, oacc[nt][3] * inv1);
    }
}

// ---------------------------------------------------------------------------
extern "C" void kernel_launch(void* const* d_in, const int* in_sizes, int n_in,
                              void* d_out, int out_size) {
    const float* x           = (const float*)d_in[0];
    const float* ln_w        = (const float*)d_in[1];
    const float* ln_b        = (const float*)d_in[2];
    const float* qkv_w       = (const float*)d_in[3];
    const float* qkv_b       = (const float*)d_in[4];
    const float* proj_w      = (const float*)d_in[5];
    const float* proj_b      = (const float*)d_in[6];
    const float* attn_biases = (const float*)d_in[7];

    void *p_xn, *p_qkv, *p_att, *p_wq, *p_wp;
    cudaGetSymbolAddress(&p_xn, g_xn);
    cudaGetSymbolAddress(&p_qkv, g_qkv);
    cudaGetSymbolAddress(&p_att, g_att);
    cudaGetSymbolAddress(&p_wq, g_wq);
    cudaGetSymbolAddress(&p_wp, g_wp);

    cudaFuncSetAttribute(hgemm_bias<1>,
                         cudaFuncAttributeMaxDynamicSharedMemorySize, G_SMEM);
    cudaFuncSetAttribute(hgemm_bias<0>,
                         cudaFuncAttributeMaxDynamicSharedMemorySize, G_SMEM);
    cudaFuncSetAttribute(attn_kernel,
                         cudaFuncAttributeMaxDynamicSharedMemorySize, ATTN_SMEM);

    // 0+1. Merged LayerNorm + weight conversion
    prep_kernel<<<LN_BLOCKS + CVT_BLOCKS, 256>>>(
        x, ln_w, ln_b, qkv_w, proj_w, (__half*)p_wq, (__half*)p_wp);

    // 2. QKV GEMM
    hgemm_bias<1><<<dim3(QKVD / 128, MROWS / 128), 256, G_SMEM>>>(
        (const __half*)p_xn, (const __half*)p_wq, qkv_b, p_qkv,
        MROWS, QKVD, DIM_N);

    // 3. Fused attention
    attn_kernel<<<dim3(N_TOK / 128, H_N, B_N), 256, ATTN_SMEM>>>(attn_biases);

    // 4. Projection GEMM -> fp32 output
    hgemm_bias<0><<<dim3(DIM_N / 128, MROWS / 128), 256, G_SMEM>>>(
        (const __half*)p_att, (const __half*)p_wp, proj_b, d_out,
        MROWS, DIM_N, DIM_N);
}

// round 17
// speedup vs baseline: 1.0047x; 1.0047x over previous
#include <cuda_runtime.h>
#include <cuda_fp16.h>
#include <math.h>
#include <stdint.h>

// Problem constants
#define B_N   16
#define N_TOK 1024
#define DIM_N 768
#define H_N   12
#define QKVD  2304
#define MROWS 16384
#define SCALE_C 0.125f
#define LOG2E 1.4426950408889634f
#define MSHIFT 4.0f
#define LN_EPS  1e-5f

// Scratch (device globals — no dynamic allocation allowed). All fp16.
__device__ __half g_xn[(size_t)MROWS * DIM_N];
__device__ __half g_qkv[(size_t)MROWS * QKVD];
__device__ __half g_att[(size_t)MROWS * DIM_N];
__device__ __half g_wq[(size_t)QKVD * DIM_N];
__device__ __half g_wp[(size_t)DIM_N * DIM_N];

// ---------------------------------------------------------------------------
// PTX helpers
// ---------------------------------------------------------------------------
__device__ __forceinline__ uint32_t sptr(const void* p) {
    return (uint32_t)__cvta_generic_to_shared(p);
}
__device__ __forceinline__ void ldmx4(uint32_t* r, uint32_t a) {
    asm volatile("ldmatrix.sync.aligned.m8n8.x4.shared.b16 {%0,%1,%2,%3}, [%4];"
                 : "=r"(r[0]), "=r"(r[1]), "=r"(r[2]), "=r"(r[3]) : "r"(a));
}
__device__ __forceinline__ void ldmx4t(uint32_t* r, uint32_t a) {
    asm volatile("ldmatrix.sync.aligned.m8n8.x4.trans.shared.b16 {%0,%1,%2,%3}, [%4];"
                 : "=r"(r[0]), "=r"(r[1]), "=r"(r[2]), "=r"(r[3]) : "r"(a));
}
__device__ __forceinline__ void mma16816(float* c, const uint32_t* a,
                                         uint32_t b0, uint32_t b1) {
    asm volatile(
        "mma.sync.aligned.m16n8k16.row.col.f32.f16.f16.f32 "
        "{%0,%1,%2,%3}, {%4,%5,%6,%7}, {%8,%9}, {%0,%1,%2,%3};"
        : "+f"(c[0]), "+f"(c[1]), "+f"(c[2]), "+f"(c[3])
        : "r"(a[0]), "r"(a[1]), "r"(a[2]), "r"(a[3]), "r"(b0), "r"(b1));
}
__device__ __forceinline__ uint32_t packh2(float x, float y) {
    __half2 h = __floats2half2_rn(x, y);
    return *(uint32_t*)&h;
}
__device__ __forceinline__ uint32_t ex2h2(uint32_t x) {
    uint32_t r;
    asm("ex2.approx.f16x2 %0, %1;" : "=r"(r) : "r"(x));
    return r;
}
// Packed fp32x2 FMA (Blackwell): d = a * sc + c, per lane, .rn — then to half2.
__device__ __forceinline__ uint32_t fma2h2(float x0, float x1,
                                           float b0, float b1, uint64_t sc) {
    uint64_t a, c, d;
    asm("mov.b64 %0, {%1, %2};" : "=l"(a) : "f"(x0), "f"(x1));
    asm("mov.b64 %0, {%1, %2};" : "=l"(c) : "f"(b0), "f"(b1));
    asm("fma.rn.f32x2 %0, %1, %2, %3;" : "=l"(d) : "l"(a), "l"(sc), "l"(c));
    float r0, r1;
    asm("mov.b64 {%0, %1}, %2;" : "=f"(r0), "=f"(r1) : "l"(d));
    return packh2(r0, r1);
}
#define CP_ASYNC(dst, src) \
    asm volatile("cp.async.cg.shared.global [%0], [%1], 16;" :: "r"(dst), "l"(src))
#define CP_COMMIT() asm volatile("cp.async.commit_group;")
#define CP_WAITN(n) asm volatile("cp.async.wait_group %0;" :: "n"(n))

// ---------------------------------------------------------------------------
// Kernel 0+1 merged: LayerNorm (blocks [0, MROWS/8)) + weight cvt (rest).
// ---------------------------------------------------------------------------
#define LN_BLOCKS (MROWS / 8)
#define NCVT ((QKVD + DIM_N) * DIM_N)
#define CVT_BLOCKS (NCVT / 1024)

__global__ void prep_kernel(const float* __restrict__ x,
                            const float* __restrict__ w,
                            const float* __restrict__ b,
                            const float* __restrict__ wq_f,
                            const float* __restrict__ wp_f,
                            __half* __restrict__ wq_h,
                            __half* __restrict__ wp_h) {
    if (blockIdx.x < LN_BLOCKS) {
        int warp = threadIdx.x >> 5, lane = threadIdx.x & 31;
        int row = blockIdx.x * 8 + warp;
        const float4* xr = (const float4*)(x + (size_t)row * DIM_N);
        float4 v[6];
        float s = 0.0f, sq = 0.0f;
        #pragma unroll
        for (int j = 0; j < 6; j++) {
            v[j] = xr[lane + 32 * j];
            s  += v[j].x + v[j].y + v[j].z + v[j].w;
            sq += v[j].x * v[j].x + v[j].y * v[j].y
                + v[j].z * v[j].z + v[j].w * v[j].w;
        }
        #pragma unroll
        for (int o = 16; o; o >>= 1) {
            s  += __shfl_xor_sync(0xffffffffu, s, o);
            sq += __shfl_xor_sync(0xffffffffu, sq, o);
        }
        float mean = s * (1.0f / DIM_N);
        float var  = sq * (1.0f / DIM_N) - mean * mean;
        float rstd = rsqrtf(var + LN_EPS);
        uint2* orow = (uint2*)(g_xn + (size_t)row * DIM_N);
        const float4* wv = (const float4*)w;
        const float4* bv = (const float4*)b;
        #pragma unroll
        for (int j = 0; j < 6; j++) {
            int idx = lane + 32 * j;
            float4 wj = wv[idx], bj = bv[idx];
            float o0 = (v[j].x - mean) * rstd * wj.x + bj.x;
            float o1 = (v[j].y - mean) * rstd * wj.y + bj.y;
            float o2 = (v[j].z - mean) * rstd * wj.z + bj.z;
            float o3 = (v[j].w - mean) * rstd * wj.w + bj.w;
            orow[idx] = make_uint2(packh2(o0, o1), packh2(o2, o3));
        }
    } else {
        const int NQ = QKVD * DIM_N;
        int i = ((blockIdx.x - LN_BLOCKS) * 256 + threadIdx.x) * 4;
        if (i < NQ) {
            float4 v = *(const float4*)(wq_f + i);
            *(__half2*)(wq_h + i)     = __floats2half2_rn(v.x, v.y);
            *(__half2*)(wq_h + i + 2) = __floats2half2_rn(v.z, v.w);
        } else {
            int k = i - NQ;
            if (k < DIM_N * DIM_N) {
                float4 v = *(const float4*)(wp_f + k);
                *(__half2*)(wp_h + k)     = __floats2half2_rn(v.x, v.y);
                *(__half2*)(wp_h + k + 2) = __floats2half2_rn(v.z, v.w);
            }
        }
    }
}

// ---------------------------------------------------------------------------
// Kernel 2/4: fp16 HMMA GEMM (R15-proven, FROZEN): 128x128 tile, BK=64,
// 8 warps (2x4), warp 64x32, 2 CTAs/SM, 3-stage cp.async ring, one barrier
// per chunk, B-fragment ping-pong across ks-steps.
// ---------------------------------------------------------------------------
#define G_STGB 32768
#define G_SMEM (3 * G_STGB)

template <int OUT_HALF>
__global__ void __launch_bounds__(256, 2)
hgemm_bias(const __half* __restrict__ A, const __half* __restrict__ W,
           const float* __restrict__ bias, void* __restrict__ Cv,
           int M, int J, int K) {
    extern __shared__ __align__(1024) char smg[];
    uint32_t sb = sptr(smg);

    int m0 = blockIdx.y * 128, j0 = blockIdx.x * 128;
    int tid = threadIdx.x, warp = tid >> 5, lane = tid & 31;
    int gid = lane >> 2, tig = lane & 3;
    int wm = (warp >> 2) * 64, wn = (warp & 3) * 32;
    int lr = tid >> 1, side = tid & 1;

    const __half* Ap = A + (size_t)(m0 + lr) * K + side * 32;
    const __half* Wp = W + (size_t)(j0 + lr) * K + side * 32;

    uint32_t sw[4];
    #pragma unroll
    for (int j = 0; j < 4; j++) {
        int c = side * 4 + j;
        sw[j] = (lr * 64 + ((c ^ (lr & 7)) * 8)) * 2;
    }

    auto fill = [&](int c, int s) {
        uint32_t as = sb + s * G_STGB;
        uint32_t bs = as + 16384;
        #pragma unroll
        for (int j = 0; j < 4; j++) {
            CP_ASYNC(as + sw[j], Ap + c * 64 + 8 * j);
            CP_ASYNC(bs + sw[j], Wp + c * 64 + 8 * j);
        }
        CP_COMMIT();
    };

    int tile = lane >> 3, rlow = lane & 7;
    int rowin = (tile & 1) * 8 + rlow;
    int chsel = tile >> 1;

    float acc[4][4][4];
    #pragma unroll
    for (int mt = 0; mt < 4; mt++)
        #pragma unroll
        for (int nt = 0; nt < 4; nt++)
            #pragma unroll
            for (int e = 0; e < 4; e++) acc[mt][nt][e] = 0.0f;

    int nk = K / 64;
    fill(0, 0); fill(1, 1); fill(2, 2);

    for (int i = 0; i < nk; i++) {
        if (i == 0)           { CP_WAITN(2); }
        else if (i < nk - 1)  { CP_WAITN(1); }
        else                  { CP_WAITN(0); }
        __syncthreads();
        if (i >= 1 && i + 2 < nk) fill(i + 2, (i + 2) % 3);

        int s = i - (i / 3) * 3;
        uint32_t Ab = sb + s * G_STGB, Bb = Ab + 16384;

        uint32_t bfr[2][8];
        {
            int ch0 = (chsel ^ rlow) * 8;
            ldmx4(&bfr[0][0], Bb + ((wn + rowin) * 64 + ch0) * 2);
            ldmx4(&bfr[0][4], Bb + ((wn + 16 + rowin) * 64 + ch0) * 2);
        }
        #pragma unroll
        for (int ks = 0; ks < 4; ks++) {
            int cur = ks & 1;
            int chunk = ((2 * ks + chsel) ^ rlow) * 8;
            uint32_t af[4][4];
            #pragma unroll
            for (int mt = 0; mt < 4; mt++)
                ldmx4(af[mt], Ab + ((wm + mt * 16 + rowin) * 64 + chunk) * 2);
            if (ks < 3) {
                int chn = ((2 * (ks + 1) + chsel) ^ rlow) * 8;
                ldmx4(&bfr[cur ^ 1][0], Bb + ((wn + rowin) * 64 + chn) * 2);
                ldmx4(&bfr[cur ^ 1][4], Bb + ((wn + 16 + rowin) * 64 + chn) * 2);
            }
            #pragma unroll
            for (int g = 0; g < 2; g++) {
                const uint32_t* r4 = &bfr[cur][g * 4];
                #pragma unroll
                for (int mt = 0; mt < 4; mt++) {
                    mma16816(acc[mt][2 * g],     af[mt], r4[0], r4[2]);
                    mma16816(acc[mt][2 * g + 1], af[mt], r4[1], r4[3]);
                }
            }
        }
    }

    #pragma unroll
    for (int mt = 0; mt < 4; mt++) {
        int row0 = m0 + wm + mt * 16 + gid;
        #pragma unroll
        for (int nt = 0; nt < 4; nt++) {
            int col = j0 + wn + nt * 8 + tig * 2;
            float b0 = bias[col], b1 = bias[col + 1];
            if (OUT_HALF) {
                __half* C = (__half*)Cv;
                *(uint32_t*)&C[(size_t)row0 * J + col] =
                    packh2(acc[mt][nt][0] + b0, acc[mt][nt][1] + b1);
                *(uint32_t*)&C[(size_t)(row0 + 8) * J + col] =
                    packh2(acc[mt][nt][2] + b0, acc[mt][nt][3] + b1);
            } else {
                float* C = (float*)Cv;
                *(float2*)&C[(size_t)row0 * J + col] =
                    make_float2(acc[mt][nt][0] + b0, acc[mt][nt][1] + b1);
                *(float2*)&C[(size_t)(row0 + 8) * J + col] =
                    make_float2(acc[mt][nt][2] + b0, acc[mt][nt][3] + b1);
            }
        }
    }
}

// ---------------------------------------------------------------------------
// Kernel 3: fused flash attention (R15 — frozen best).
// 3-stage super-stage K/V ring (2 key-tiles per barrier), static-shift log2
// softmax (FFMA2 + ex2.f16x2), ones-MMA row sums, V-fragment prefetch,
// hoisted Q frags and bias indexing.
// ---------------------------------------------------------------------------
#define ATTN_SMEM 102528

__global__ void __launch_bounds__(256, 2)
attn_kernel(const float* __restrict__ biases) {
    extern __shared__ __align__(1024) char sma[];
    float* b_s = (float*)(sma + 98304);
    uint32_t Kb = sptr(sma);
    uint32_t Vb = Kb + 49152;
    __half* Qstage = (__half*)(sma + 49152);

    int qt = blockIdx.x, h = blockIdx.y, b = blockIdx.z;
    int tid = threadIdx.x, warp = tid >> 5, lane = tid & 31;
    int gid = lane >> 2, tig = lane & 3;
    int n0 = qt * 128;
    const float SCALE2 = SCALE_C * LOG2E;
    uint64_t sc2;
    asm("mov.b64 %0, {%1, %1};" : "=l"(sc2) : "f"(SCALE2));

    for (int i = tid; i < 1024; i += 256) {
        int dy = i >> 5, dx = i & 31;
        b_s[dx * 33 + dy] = biases[h * 1024 + i] * LOG2E - MSHIFT;
    }

    {
        int r = tid >> 1, side = tid & 1;
        const __half* qp = g_qkv + (size_t)(b * N_TOK + n0 + r) * QKVD
                           + h * 192 + side * 32;
        #pragma unroll
        for (int j = 0; j < 4; j++) {
            int c = side * 4 + j;
            *(uint4*)&Qstage[r * 64 + ((c ^ (r & 7)) * 8)] =
                *(const uint4*)(qp + 8 * j);
        }
    }
    __syncthreads();

    int tile = lane >> 3, rlow = lane & 7;
    int rowin = (tile & 1) * 8 + rlow;
    int chsel = tile >> 1;

    uint32_t qfrag[4][4];
    #pragma unroll
    for (int ks = 0; ks < 4; ks++) {
        int chunk = ((2 * ks + chsel) ^ rlow) * 8;
        ldmx4(qfrag[ks], Vb + ((warp * 16 + rowin) * 64 + chunk) * 2);
    }
    __syncthreads();

    uint32_t ones01 = (gid == 0) ? 0x3C003C00u : 0u;

    int q0 = n0 + warp * 16 + gid, q1 = q0 + 8;
    int yq0 = q0 >> 5, xq0 = q0 & 31;
    int yq1 = q1 >> 5, xq1 = q1 & 31;
    int dx0t[8], dx1t[8];
    #pragma unroll
    for (int v = 0; v < 8; v++) {
        int xm = (v >> 1) * 8 + tig * 2 + (v & 1);
        dx0t[v] = abs(xq0 - xm) * 33;
        dx1t[v] = abs(xq1 - xm) * 33;
    }

    int fr = tid >> 2, fq = tid & 3;
    uint32_t fsw[2];
    #pragma unroll
    for (int j = 0; j < 2; j++) {
        int c = fq * 2 + j;
        fsw[j] = (fr * 64 + ((c ^ (fr & 7)) * 8)) * 2;
    }
    auto fillkv2 = [&](int j2, int s) {
        #pragma unroll
        for (int t = 0; t < 2; t++) {
            int kt = 2 * j2 + t;
            const __half* kp = g_qkv + (size_t)(b * N_TOK + kt * 64 + fr) * QKVD
                               + h * 192 + 64 + fq * 16;
            const __half* vp = kp + 64;
            uint32_t off = s * 16384 + t * 8192;
            #pragma unroll
            for (int j = 0; j < 2; j++) {
                CP_ASYNC(Kb + off + fsw[j], kp + 8 * j);
                CP_ASYNC(Vb + off + fsw[j], vp + 8 * j);
            }
        }
        CP_COMMIT();
    };

    float oacc[8][4], lacc[4];
    #pragma unroll
    for (int nt = 0; nt < 8; nt++)
        #pragma unroll
        for (int e = 0; e < 4; e++) oacc[nt][e] = 0.0f;
    #pragma unroll
    for (int e = 0; e < 4; e++) lacc[e] = 0.0f;

    fillkv2(0, 0); fillkv2(1, 1); fillkv2(2, 2);

    for (int j2 = 0; j2 < 8; j2++) {
        if (j2 == 0)      { CP_WAITN(2); }
        else if (j2 < 7)  { CP_WAITN(1); }
        else              { CP_WAITN(0); }
        __syncthreads();
        if (j2 >= 1 && j2 + 2 < 8) fillkv2(j2 + 2, (j2 + 2) % 3);

        int s = j2 - (j2 / 3) * 3;
        #pragma unroll
        for (int t = 0; t < 2; t++) {
            int tt = 2 * j2 + t;
            uint32_t Kcur = Kb + s * 16384 + t * 8192;
            uint32_t Vcur = Vb + s * 16384 + t * 8192;

            float sacc[8][4];
            #pragma unroll
            for (int nt = 0; nt < 8; nt++)
                #pragma unroll
                for (int e = 0; e < 4; e++) sacc[nt][e] = 0.0f;

            #pragma unroll
            for (int ks = 0; ks < 4; ks++) {
                int chunk = ((2 * ks + chsel) ^ rlow) * 8;
                #pragma unroll
                for (int g = 0; g < 2; g++) {
                    uint32_t r4[4];
                    ldmx4(r4, Kcur + ((g * 16 + rowin) * 64 + chunk) * 2);
                    mma16816(sacc[2 * g],     qfrag[ks], r4[0], r4[2]);
                    mma16816(sacc[2 * g + 1], qfrag[ks], r4[1], r4[3]);
                }
            }
            #pragma unroll
            for (int ks = 0; ks < 4; ks++) {
                int chunk = ((2 * ks + chsel) ^ rlow) * 8;
                #pragma unroll
                for (int g = 2; g < 4; g++) {
                    uint32_t r4[4];
                    ldmx4(r4, Kcur + ((g * 16 + rowin) * 64 + chunk) * 2);
                    mma16816(sacc[2 * g],     qfrag[ks], r4[0], r4[2]);
                    mma16816(sacc[2 * g + 1], qfrag[ks], r4[1], r4[3]);
                }
            }

            uint32_t vfA0[4][4];
            #pragma unroll
            for (int g = 0; g < 4; g++) {
                int row = rowin;
                ldmx4t(vfA0[g], Vcur + (row * 64 + (((2 * g + chsel) ^ (row & 7)) * 8)) * 2);
            }

            int dy0A = abs(yq0 - 2 * tt), dy1A = abs(yq1 - 2 * tt);
            uint32_t pfragA[2][4];
            #pragma unroll
            for (int c = 0; c < 2; c++) {
                int v0 = (2 * c) * 2, v1 = (2 * c + 1) * 2;
                pfragA[c][0] = ex2h2(fma2h2(sacc[2 * c][0], sacc[2 * c][1],
                                            b_s[dx0t[v0] + dy0A],
                                            b_s[dx0t[v0 + 1] + dy0A], sc2));
                pfragA[c][1] = ex2h2(fma2h2(sacc[2 * c][2], sacc[2 * c][3],
                                            b_s[dx1t[v0] + dy1A],
                                            b_s[dx1t[v0 + 1] + dy1A], sc2));
                pfragA[c][2] = ex2h2(fma2h2(sacc[2 * c + 1][0], sacc[2 * c + 1][1],
                                            b_s[dx0t[v1] + dy0A],
                                            b_s[dx0t[v1 + 1] + dy0A], sc2));
                pfragA[c][3] = ex2h2(fma2h2(sacc[2 * c + 1][2], sacc[2 * c + 1][3],
                                            b_s[dx1t[v1] + dy1A],
                                            b_s[dx1t[v1 + 1] + dy1A], sc2));
            }

            mma16816(lacc, pfragA[0], ones01, ones01);
            #pragma unroll
            for (int g = 0; g < 4; g++) {
                mma16816(oacc[2 * g],     pfragA[0], vfA0[g][0], vfA0[g][1]);
                mma16816(oacc[2 * g + 1], pfragA[0], vfA0[g][2], vfA0[g][3]);
            }
            mma16816(lacc, pfragA[1], ones01, ones01);
            #pragma unroll
            for (int g = 0; g < 4; g++) {
                uint32_t r4[4];
                int row = 16 + rowin;
                ldmx4t(r4, Vcur + (row * 64 + (((2 * g + chsel) ^ (row & 7)) * 8)) * 2);
                mma16816(oacc[2 * g],     pfragA[1], r4[0], r4[1]);
                mma16816(oacc[2 * g + 1], pfragA[1], r4[2], r4[3]);
            }

            uint32_t vfB0[4][4];
            #pragma unroll
            for (int g = 0; g < 4; g++) {
                int row = 32 + rowin;
                ldmx4t(vfB0[g], Vcur + (row * 64 + (((2 * g + chsel) ^ (row & 7)) * 8)) * 2);
            }

            int dy0B = abs(yq0 - 2 * tt - 1), dy1B = abs(yq1 - 2 * tt - 1);
            uint32_t pfragB[2][4];
            #pragma unroll
            for (int c = 0; c < 2; c++) {
                int v0 = (2 * c) * 2, v1 = (2 * c + 1) * 2;
                pfragB[c][0] = ex2h2(fma2h2(sacc[4 + 2 * c][0], sacc[4 + 2 * c][1],
                                            b_s[dx0t[v0] + dy0B],
                                            b_s[dx0t[v0 + 1] + dy0B], sc2));
                pfragB[c][1] = ex2h2(fma2h2(sacc[4 + 2 * c][2], sacc[4 + 2 * c][3],
                                            b_s[dx1t[v0] + dy1B],
                                            b_s[dx1t[v0 + 1] + dy1B], sc2));
                pfragB[c][2] = ex2h2(fma2h2(sacc[5 + 2 * c][0], sacc[5 + 2 * c][1],
                                            b_s[dx0t[v1] + dy0B],
                                            b_s[dx0t[v1 + 1] + dy0B], sc2));
                pfragB[c][3] = ex2h2(fma2h2(sacc[5 + 2 * c][2], sacc[5 + 2 * c][3],
                                            b_s[dx1t[v1] + dy1B],
                                            b_s[dx1t[v1 + 1] + dy1B], sc2));
            }

            mma16816(lacc, pfragB[0], ones01, ones01);
            #pragma unroll
            for (int g = 0; g < 4; g++) {
                mma16816(oacc[2 * g],     pfragB[0], vfB0[g][0], vfB0[g][1]);
                mma16816(oacc[2 * g + 1], pfragB[0], vfB0[g][2], vfB0[g][3]);
            }
            mma16816(lacc, pfragB[1], ones01, ones01);
            #pragma unroll
            for (int g = 0; g < 4; g++) {
                uint32_t r4[4];
                int row = 48 + rowin;
                ldmx4t(r4, Vcur + (row * 64 + (((2 * g + chsel) ^ (row & 7)) * 8)) * 2);
                mma16816(oacc[2 * g],     pfragB[1], r4[0], r4[1]);
                mma16816(oacc[2 * g + 1], pfragB[1], r4[2], r4[3]);
            }
        }
    }

    float l0 = __shfl_sync(0xffffffffu, lacc[0], lane & 28);
    float l1 = __shfl_sync(0xffffffffu, lacc[2], lane & 28);
    float inv0 = 1.0f / l0, inv1 = 1.0f / l1;
    size_t row0 = (size_t)(b * N_TOK + n0 + warp * 16 + gid) * DIM_N;
    size_t row1 = row0 + 8 * DIM_N;
    #pragma unroll
    for (int nt = 0; nt < 8; nt++) {
        int col = h * 64 + nt * 8 + tig * 2;
        *(uint32_t*)&g_att[row0 + col] =
            packh2(oacc[nt][0] * inv0, oacc[nt][1] * inv0);
        *(uint32_t*)&g_att[row1 + col] =
            packh2(oacc[nt][2] * inv1, oacc[nt][3] * inv1);
    }
}

// ---------------------------------------------------------------------------
extern "C" void kernel_launch(void* const* d_in, const int* in_sizes, int n_in,
                              void* d_out, int out_size) {
    const float* x           = (const float*)d_in[0];
    const float* ln_w        = (const float*)d_in[1];
    const float* ln_b        = (const float*)d_in[2];
    const float* qkv_w       = (const float*)d_in[3];
    const float* qkv_b       = (const float*)d_in[4];
    const float* proj_w      = (const float*)d_in[5];
    const float* proj_b      = (const float*)d_in[6];
    const float* attn_biases = (const float*)d_in[7];

    void *p_xn, *p_qkv, *p_att, *p_wq, *p_wp;
    cudaGetSymbolAddress(&p_xn, g_xn);
    cudaGetSymbolAddress(&p_qkv, g_qkv);
    cudaGetSymbolAddress(&p_att, g_att);
    cudaGetSymbolAddress(&p_wq, g_wq);
    cudaGetSymbolAddress(&p_wp, g_wp);

    cudaFuncSetAttribute(hgemm_bias<1>,
                         cudaFuncAttributeMaxDynamicSharedMemorySize, G_SMEM);
    cudaFuncSetAttribute(hgemm_bias<0>,
                         cudaFuncAttributeMaxDynamicSharedMemorySize, G_SMEM);
    cudaFuncSetAttribute(attn_kernel,
                         cudaFuncAttributeMaxDynamicSharedMemorySize, ATTN_SMEM);

    // 0+1. Merged LayerNorm + weight conversion
    prep_kernel<<<LN_BLOCKS + CVT_BLOCKS, 256>>>(
        x, ln_w, ln_b, qkv_w, proj_w, (__half*)p_wq, (__half*)p_wp);

    // 2. QKV GEMM
    hgemm_bias<1><<<dim3(QKVD / 128, MROWS / 128), 256, G_SMEM>>>(
        (const __half*)p_xn, (const __half*)p_wq, qkv_b, p_qkv,
        MROWS, QKVD, DIM_N);

    // 3. Fused attention
    attn_kernel<<<dim3(N_TOK / 128, H_N, B_N), 256, ATTN_SMEM>>>(attn_biases);

    // 4. Projection GEMM -> fp32 output
    hgemm_bias<0><<<dim3(DIM_N / 128, MROWS / 128), 256, G_SMEM>>>(
        (const __half*)p_att, (const __half*)p_wp, proj_b, d_out,
        MROWS, DIM_N, DIM_N);
}